// round 15
// baseline (speedup 1.0000x reference)
#include <cuda_runtime.h>
#include <math.h>

// BinEmbedding: out[p] = emb_table[tok(x[p])]
//   tok = 0 if isnan(x), else clamp(count(bins <= x) - 1, 0) + 1
//
// x (B*L,) f32, bins (256,) f32, emb_table (257*64,) f32,
// out (B*L, 64) f32 = 268 MB written.
//
// FINAL converged kernel (best in-window measurement: ncu 41.79us,
// DRAM 64.4%, wall ~43us = 6.3 TB/s = LTS chip cap):
//  - shared bins table, loaded once per block (single barrier)
//  - warp w searches exactly the 32 rows it stores:
//      lane -> row = 2*w + (lane>>1)*16 + (lane&1)
//    tokens stay register-resident, exchanged via __shfl_sync
//    (copy iter k sources lane 2k + (lane>>4)) -> no stok smem,
//    no post-search barrier
//  - copy: sub-invariant LDG.128 gathers from the L1-resident 64KB table,
//    8-wide independent batches (MLP~8), .cs streaming STG.128
//  - PPB 256 / 256 threads / grid 4096 (best wave balance measured)

#define NUM_BINS 256
#define F4_PER_ROW 16                    // 64 floats / 4
#define THREADS 256
#define PPB 256                          // positions per block
#define COPY_ITERS 16
#define BATCH 8

__global__ __launch_bounds__(THREADS) void bin_embed_kernel(
    const float*  __restrict__ x,
    const float*  __restrict__ bins,
    const float4* __restrict__ emb4,     // (NUM_BINS+1) * 16 float4
    float4*       __restrict__ out)      // n_pos * 16 float4
{
    __shared__ float sbins[NUM_BINS];

    const int tid  = threadIdx.x;
    const int base = blockIdx.x * PPB;
    const int warp = tid >> 5;
    const int lane = tid & 31;

    sbins[tid] = bins[tid];              // THREADS == NUM_BINS
    __syncthreads();

    // ---- Phase 1: each warp searches the 32 rows it will store ----
    // lane -> row = 2*warp + (lane>>1)*16 + (lane&1)
    int my_tok;
    {
        int my_row = 2 * warp + ((lane >> 1) << 4) + (lane & 1);
        float v = __ldg(&x[base + my_row]);
        int c = 0;
        bool nn = isnan(v);
        #pragma unroll
        for (int s = NUM_BINS >> 1; s > 0; s >>= 1) {
            if (sbins[c + s - 1] <= v) c += s;
        }
        int i0 = c - 1; if (i0 < 0) i0 = 0;
        my_tok = nn ? 0 : i0 + 1;
    }
    // Tokens live in registers; exchanged via shuffle. No second barrier.

    // ---- Phase 2: gather + coalesced streaming stores, 8-wide batches ----
    // float4 element index = tid + k*THREADS; sub = tid & 15 invariant.
    // Token source lane for iter k: 2k + (lane>>4).
    const int sub  = tid & 15;
    const int half = lane >> 4;          // 0 for lanes 0-15, 1 for 16-31
    float4* outp   = out + (size_t)base * F4_PER_ROW + tid;

    #pragma unroll
    for (int b = 0; b < COPY_ITERS / BATCH; b++) {   // 2 batches
        int tok[BATCH];
        #pragma unroll
        for (int k = 0; k < BATCH; k++) {
            int kk = b * BATCH + k;
            tok[k] = __shfl_sync(0xFFFFFFFFu, my_tok, 2 * kk + half);
        }

        float4 val[BATCH];
        #pragma unroll
        for (int k = 0; k < BATCH; k++)
            val[k] = __ldg(&emb4[tok[k] * F4_PER_ROW + sub]);

        #pragma unroll
        for (int k = 0; k < BATCH; k++)
            __stcs(outp + (size_t)k * THREADS, val[k]);

        outp += (size_t)BATCH * THREADS;
    }
}

extern "C" void kernel_launch(void* const* d_in, const int* in_sizes, int n_in,
                              void* d_out, int out_size)
{
    const float*  x    = (const float*)d_in[0];
    const float*  bins = (const float*)d_in[1];
    const float4* emb4 = (const float4*)d_in[2];
    float4* out = (float4*)d_out;

    int n_pos  = in_sizes[0];            // 1,048,576; divisible by PPB
    int blocks = n_pos / PPB;            // 4096

    bin_embed_kernel<<<blocks, THREADS>>>(x, bins, emb4, out);
}

// round 16
// speedup vs baseline: 1.0097x; 1.0097x over previous
#include <cuda_runtime.h>
#include <math.h>

// BinEmbedding: out[p] = emb_table[tok(x[p])]
//   tok = 0 if isnan(x), else clamp(count(bins <= x) - 1, 0) + 1
//
// x (B*L,) f32, bins (256,) f32, emb_table (257*64,) f32,
// out (B*L, 64) f32 = 268 MB written.
//
// FINAL converged kernel. Best reproducible wall clock: 43.01us measured
// twice (plus 43.04) = 272MB / 43us = 6.3 TB/s = the measured LTS chip cap
// (path-independent; TMA store variant was exactly neutral). All axes
// exhausted over 15 rounds: store width/path/policy, tile size 1024->128,
// MLP 4/8/16, occupancy 25-86%, token transport (smem vs SHFL), bins
// placement, search ILP. This config is the measured optimum:
//   - PPB 256, 256 threads, grid 4096 (best wave balance)
//   - one binary search per position (tokens staged in smem, one barrier)
//   - copy phase: sub-invariant LDG.128 gathers from the L1-resident 64KB
//     table, 8-wide independent batches (MLP~8), .cs streaming STG.128

#define NUM_BINS 256
#define F4_PER_ROW 16                    // 64 floats / 4
#define THREADS 256
#define PPB 256                          // positions per block
#define COPY_ITERS (PPB * F4_PER_ROW / THREADS)   // 16
#define BATCH 8

__global__ __launch_bounds__(THREADS) void bin_embed_kernel(
    const float*  __restrict__ x,
    const float*  __restrict__ bins,
    const float4* __restrict__ emb4,     // (NUM_BINS+1) * 16 float4
    float4*       __restrict__ out)      // n_pos * 16 float4
{
    __shared__ float sbins[NUM_BINS];
    __shared__ int   stok[PPB];

    const int tid  = threadIdx.x;
    const int base = blockIdx.x * PPB;

    sbins[tid] = bins[tid];              // THREADS == NUM_BINS
    __syncthreads();

    // ---- Phase 1: one search per thread ----
    {
        float v = __ldg(&x[base + tid]);
        int c = 0;
        bool nn = isnan(v);
        #pragma unroll
        for (int s = NUM_BINS >> 1; s > 0; s >>= 1) {
            if (sbins[c + s - 1] <= v) c += s;
        }
        int i0 = c - 1; if (i0 < 0) i0 = 0;
        stok[tid] = nn ? 0 : i0 + 1;
    }
    __syncthreads();

    // ---- Phase 2: gather + coalesced streaming stores, 8-wide batches ----
    // float4 element index = tid + k*THREADS; sub = tid & 15 invariant;
    // row advances by 16 per iteration.
    const int sub = tid & 15;
    int row       = tid >> 4;
    float4* outp  = out + (size_t)base * F4_PER_ROW + tid;

    #pragma unroll
    for (int b = 0; b < COPY_ITERS / BATCH; b++) {   // 2 batches
        int tok[BATCH];
        #pragma unroll
        for (int k = 0; k < BATCH; k++) tok[k] = stok[row + k * 16];

        float4 val[BATCH];
        #pragma unroll
        for (int k = 0; k < BATCH; k++)
            val[k] = __ldg(&emb4[tok[k] * F4_PER_ROW + sub]);

        #pragma unroll
        for (int k = 0; k < BATCH; k++)
            __stcs(outp + (size_t)k * THREADS, val[k]);

        row  += BATCH * 16;
        outp += (size_t)BATCH * THREADS;
    }
}

extern "C" void kernel_launch(void* const* d_in, const int* in_sizes, int n_in,
                              void* d_out, int out_size)
{
    const float*  x    = (const float*)d_in[0];
    const float*  bins = (const float*)d_in[1];
    const float4* emb4 = (const float4*)d_in[2];
    float4* out = (float4*)d_out;

    int n_pos  = in_sizes[0];            // 1,048,576; divisible by PPB
    int blocks = n_pos / PPB;            // 4096

    bin_embed_kernel<<<blocks, THREADS>>>(x, bins, emb4, out);
}